// round 5
// baseline (speedup 1.0000x reference)
#include <cuda_runtime.h>
#include <cuda_fp16.h>
#include <cuda_bf16.h>
#include <cstdint>
#include <cstddef>

#define TT   4096
#define HID  2048
#define INW  2048
#define G4   (4*HID)

#define NCTA     148
#define HPC      14
#define NROWS    (HPC*4)
#define RTHREADS 448
#define REC_SMEM (NROWS*HID*2)   // 229376 B fp16 W_hh rows (< 227KB opt-in limit)

// ---------------- scratch layout ----------------
#define OFF_GX    ((size_t)0)                            // float [T][4H]
#define OFF_XH    (OFF_GX   + (size_t)TT*G4*4)           // half  [T][I] hi
#define OFF_XL    (OFF_XH   + (size_t)TT*INW*2)          // half  [T][I] lo
#define OFF_WIH   (OFF_XL   + (size_t)TT*INW*2)          // half  [4H][I] hi
#define OFF_WIL   (OFF_WIH  + (size_t)G4*INW*2)          // half  [4H][I] lo
#define OFF_WO    (OFF_WIL  + (size_t)G4*INW*2)          // half  [I][H] hi
#define OFF_HS    (OFF_WO   + (size_t)INW*HID*2)         // half  [T][H]
#define OFF_BIAS  (OFF_HS   + (size_t)TT*HID*2)          // float [4H]
#define OFF_HBUF  (OFF_BIAS + (size_t)G4*4)              // float [2][H]
#define OFF_BAR   (OFF_HBUF + (size_t)2*HID*4)           // counter + 8 release words
#define SCRATCH_BYTES (OFF_BAR + 4096)

__device__ __align__(256) unsigned char g_scratch[SCRATCH_BYTES];

__device__ __forceinline__ float sigf(float x){ return 1.0f / (1.0f + __expf(-x)); }
__device__ __forceinline__ float tanh_fast(float x){
    float e = __expf(2.0f * x);              // inf-safe: e=inf -> 1; e=0 -> -1
    return 1.0f - 2.0f / (e + 1.0f);
}
__device__ __forceinline__ float2 h2f(unsigned u){
    __half2 h = *reinterpret_cast<__half2*>(&u);
    return __half22float2(h);
}
__device__ __forceinline__ void red_release_add(unsigned* p){
    asm volatile("red.release.gpu.global.add.u32 [%0], 1;" :: "l"(p) : "memory");
}
__device__ __forceinline__ unsigned ld_acquire(const unsigned* p){
    unsigned v;
    asm volatile("ld.acquire.gpu.global.u32 %0, [%1];" : "=r"(v) : "l"(p) : "memory");
    return v;
}
__device__ __forceinline__ void st_release(unsigned* p, unsigned v){
    asm volatile("st.release.gpu.global.u32 [%0], %1;" :: "l"(p), "r"(v) : "memory");
}

// ---------------- conversion / setup ----------------
__global__ void f2h_split_kernel(const float* __restrict__ in, __half* __restrict__ hi,
                                 __half* __restrict__ lo, int n){
    int i = (blockIdx.x * blockDim.x + threadIdx.x) * 4;
    int stride = gridDim.x * blockDim.x * 4;
    for (; i < n; i += stride){
        float4 v = *(const float4*)(in + i);
        __half h0 = __float2half_rn(v.x), h1 = __float2half_rn(v.y);
        __half h2 = __float2half_rn(v.z), h3 = __float2half_rn(v.w);
        ((__half2*)(hi + i))[0] = __halves2half2(h0, h1);
        ((__half2*)(hi + i))[1] = __halves2half2(h2, h3);
        ((__half2*)(lo + i))[0] = __halves2half2(
            __float2half_rn(v.x - __half2float(h0)), __float2half_rn(v.y - __half2float(h1)));
        ((__half2*)(lo + i))[1] = __halves2half2(
            __float2half_rn(v.z - __half2float(h2)), __float2half_rn(v.w - __half2float(h3)));
    }
}

__global__ void setup_kernel(const float* __restrict__ a, const float* __restrict__ b,
                             float* __restrict__ o, unsigned* __restrict__ bar){
    int i = blockIdx.x * blockDim.x + threadIdx.x;
    if (i < G4) o[i] = a[i] + b[i];
    if (blockIdx.x == 0 && threadIdx.x < 1024) bar[threadIdx.x] = 0u;
}

// ---------------- fp16 NT GEMM (mma.sync, f32 accum) ----------------
__device__ __forceinline__ void cp_async16(void* smem, const void* g){
    unsigned s = (unsigned)__cvta_generic_to_shared(smem);
    asm volatile("cp.async.cg.shared.global [%0], [%1], 16;\n" :: "r"(s), "l"(g));
}
__device__ __forceinline__ void cp_commit(){ asm volatile("cp.async.commit_group;\n"); }
template<int N> __device__ __forceinline__ void cp_wait(){
    asm volatile("cp.async.wait_group %0;\n" :: "n"(N));
}
__device__ __forceinline__ void mma16816(float* c, const unsigned* a, const unsigned* b){
    asm volatile(
        "mma.sync.aligned.m16n8k16.row.col.f32.f16.f16.f32 "
        "{%0,%1,%2,%3}, {%4,%5,%6,%7}, {%8,%9}, {%0,%1,%2,%3};"
        : "+f"(c[0]), "+f"(c[1]), "+f"(c[2]), "+f"(c[3])
        : "r"(a[0]), "r"(a[1]), "r"(a[2]), "r"(a[3]), "r"(b[0]), "r"(b[1]));
}

#define GSTRIDE 40   // halves per smem row: 32 data + 8 pad (80B, 16B aligned)

template<int SIG, int ACC>
__global__ __launch_bounds__(256, 1)
void gemm_nt_kernel(const __half* __restrict__ A, const __half* __restrict__ B,
                    const float* __restrict__ bias, float* __restrict__ C,
                    int M, int N, int K){
    __shared__ __half As[2][128 * GSTRIDE];
    __shared__ __half Bs[2][128 * GSTRIDE];
    const int tid = threadIdx.x, wid = tid >> 5, l = tid & 31;
    const int wm = wid & 1, wn = wid >> 1;            // 2x4 warps, 64x32 warp tile
    const int m0 = blockIdx.y * 128, n0 = blockIdx.x * 128;

    float acc[4][4][4];
    #pragma unroll
    for (int i = 0; i < 4; ++i)
        #pragma unroll
        for (int j = 0; j < 4; ++j)
            #pragma unroll
            for (int q = 0; q < 4; ++q) acc[i][j][q] = 0.0f;

    const int NT = K / 32;
    auto load_stage = [&](int s, int kt){
        #pragma unroll
        for (int i = 0; i < 2; ++i){
            int c = tid + i * 256;
            int r = c >> 2, ch = c & 3;
            cp_async16(&As[s][r * GSTRIDE + ch * 8], A + (size_t)(m0 + r) * K + kt + ch * 8);
            cp_async16(&Bs[s][r * GSTRIDE + ch * 8], B + (size_t)(n0 + r) * K + kt + ch * 8);
        }
        cp_commit();
    };

    load_stage(0, 0);
    for (int t = 0; t < NT; ++t){
        if (t + 1 < NT){ load_stage((t + 1) & 1, (t + 1) * 32); cp_wait<1>(); }
        else           { cp_wait<0>(); }
        __syncthreads();
        const __half* Asb = As[t & 1];
        const __half* Bsb = Bs[t & 1];
        #pragma unroll
        for (int k16 = 0; k16 < 2; ++k16){
            unsigned a[4][4], b[4][2];
            const int cc = k16 * 16 + (l & 3) * 2;
            #pragma unroll
            for (int i = 0; i < 4; ++i){
                int r = wm * 64 + i * 16 + (l >> 2);
                a[i][0] = *(const unsigned*)(Asb + r * GSTRIDE + cc);
                a[i][1] = *(const unsigned*)(Asb + (r + 8) * GSTRIDE + cc);
                a[i][2] = *(const unsigned*)(Asb + r * GSTRIDE + cc + 8);
                a[i][3] = *(const unsigned*)(Asb + (r + 8) * GSTRIDE + cc + 8);
            }
            #pragma unroll
            for (int j = 0; j < 4; ++j){
                int r = wn * 32 + j * 8 + (l >> 2);
                b[j][0] = *(const unsigned*)(Bsb + r * GSTRIDE + cc);
                b[j][1] = *(const unsigned*)(Bsb + r * GSTRIDE + cc + 8);
            }
            #pragma unroll
            for (int i = 0; i < 4; ++i)
                #pragma unroll
                for (int j = 0; j < 4; ++j)
                    mma16816(acc[i][j], a[i], b[j]);
        }
        __syncthreads();
    }

    #pragma unroll
    for (int i = 0; i < 4; ++i){
        #pragma unroll
        for (int j = 0; j < 4; ++j){
            int rm = m0 + wm * 64 + i * 16 + (l >> 2);
            int cn = n0 + wn * 32 + j * 8 + (l & 3) * 2;
            float2* p0 = (float2*)(C + (size_t)rm * N + cn);
            float2* p1 = (float2*)(C + (size_t)(rm + 8) * N + cn);
            float v0, v1, v2, v3;
            if (ACC){
                float2 o0 = *p0, o1 = *p1;
                v0 = acc[i][j][0] + o0.x; v1 = acc[i][j][1] + o0.y;
                v2 = acc[i][j][2] + o1.x; v3 = acc[i][j][3] + o1.y;
            } else {
                float b0 = bias[cn], b1 = bias[cn + 1];
                v0 = acc[i][j][0] + b0; v1 = acc[i][j][1] + b1;
                v2 = acc[i][j][2] + b0; v3 = acc[i][j][3] + b1;
                if (SIG){ v0 = sigf(v0); v1 = sigf(v1); v2 = sigf(v2); v3 = sigf(v3); }
            }
            *p0 = make_float2(v0, v1);
            *p1 = make_float2(v2, v3);
        }
    }
}

// ---------------- persistent LSTM recurrence ----------------
// 148 CTAs (1/SM). CTA c owns h-elements [c*14, c*14+14); their 56 W_hh rows
// live in SMEM as fp16 (224KB). One warp per h-element; fp32 accumulate;
// arrive(red.release) / leader-poll / 8-way release-broadcast grid barrier.
__global__ __launch_bounds__(RTHREADS, 1)
void lstm_rec_kernel(const float* __restrict__ Whh, const float* __restrict__ gx,
                     __half* __restrict__ hs, float* __restrict__ hbuf,
                     unsigned* __restrict__ bar){
    extern __shared__ uint4 smW[];                    // [56][256] uint4 = 2048 fp16/row
    unsigned* smw32 = (unsigned*)smW;
    const int tid = threadIdx.x;
    const int w = tid >> 5, l = tid & 31;
    const int cta = blockIdx.x;
    unsigned* rel = bar + 64;                         // 8 words, 256B apart

    // load + convert this CTA's W_hh rows to fp16 in SMEM
    for (int idx = tid; idx < NROWS * 1024; idx += RTHREADS){
        int sr = idx >> 10, wc = idx & 1023;
        int e = cta * HPC + (sr >> 2);
        int gate = sr & 3;
        unsigned val = 0u;
        if (e < HID){
            const float2 f2 = *(const float2*)(Whh + (size_t)(gate * HID + e) * HID + 2 * wc);
            unsigned lo = (unsigned)__half_as_ushort(__float2half_rn(f2.x));
            unsigned hi = (unsigned)__half_as_ushort(__float2half_rn(f2.y));
            val = (hi << 16) | lo;
        }
        smw32[sr * 1024 + wc] = val;
    }
    if (tid < HPC){
        int e = cta * HPC + tid;
        if (e < HID) hbuf[e] = 0.0f;
    }
    __syncthreads();

    // init barrier (phase 1): h zeros complete grid-wide
    if (tid == 0){
        red_release_add(bar);
        if (cta == 0){
            while (ld_acquire(bar) < (unsigned)NCTA) { }
            #pragma unroll
            for (int i = 0; i < 8; ++i) st_release(rel + i * 64, 1u);
        }
        const unsigned* mr = rel + (cta & 7) * 64;
        while (ld_acquire(mr) < 1u) __nanosleep(32);
    }
    __syncthreads();

    const int e = cta * HPC + w;
    const bool active = (e < HID);
    const int w4 = w * 4;
    float c = 0.0f;

    #pragma unroll 1
    for (int t = 0; t < TT; ++t){
        const float* hr = hbuf + (t & 1) * HID;
        float*       hw = hbuf + ((t + 1) & 1) * HID;

        float gx0 = 0.f, gx1 = 0.f, gx2 = 0.f, gx3 = 0.f;
        if (active){
            const float* gp = gx + (size_t)t * G4 + e;
            gx0 = __ldcg(gp);
            gx1 = __ldcg(gp + HID);
            gx2 = __ldcg(gp + 2 * HID);
            gx3 = __ldcg(gp + 3 * HID);
        }

        // lane l covers h columns [8l+256j, 8l+256j+8), j=0..7
        float4 hv[16];
        #pragma unroll
        for (int j = 0; j < 8; ++j){
            hv[2 * j]     = __ldcg((const float4*)hr + 2 * l + 64 * j);
            hv[2 * j + 1] = __ldcg((const float4*)hr + 2 * l + 64 * j + 1);
        }

        float acc[4] = {0.f, 0.f, 0.f, 0.f};
        #pragma unroll
        for (int j = 0; j < 8; ++j){
            float4 ha = hv[2 * j], hb = hv[2 * j + 1];
            #pragma unroll
            for (int g = 0; g < 4; ++g){
                uint4 wv = smW[(w4 + g) * 256 + l + 32 * j];
                float2 w0 = h2f(wv.x), w1 = h2f(wv.y), w2 = h2f(wv.z), w3 = h2f(wv.w);
                float s = acc[g];
                s += w0.x * ha.x;  s += w0.y * ha.y;
                s += w1.x * ha.z;  s += w1.y * ha.w;
                s += w2.x * hb.x;  s += w2.y * hb.y;
                s += w3.x * hb.z;  s += w3.y * hb.w;
                acc[g] = s;
            }
        }
        #pragma unroll
        for (int off = 16; off; off >>= 1){
            acc[0] += __shfl_xor_sync(0xffffffffu, acc[0], off);
            acc[1] += __shfl_xor_sync(0xffffffffu, acc[1], off);
            acc[2] += __shfl_xor_sync(0xffffffffu, acc[2], off);
            acc[3] += __shfl_xor_sync(0xffffffffu, acc[3], off);
        }

        if (active && l == 0){
            float gi = acc[0] + gx0;
            float gf = acc[1] + gx1;
            float gg = acc[2] + gx2;
            float go = acc[3] + gx3;
            float ig = sigf(gi), fg = sigf(gf), og = sigf(go);
            float gt = tanh_fast(gg);
            c = fg * c + ig * gt;
            float hn = og * tanh_fast(c);
            __stcg(&hw[e], hn);
            __stcg(&hs[(size_t)t * HID + e], __float2half(hn));
        }

        // grid barrier: arrive -> leader polls counter -> 8-way release bcast
        __syncthreads();
        if (tid == 0){
            red_release_add(bar);                    // release: publishes h stores
            const unsigned ph = (unsigned)(t + 2);
            if (cta == 0){
                while (ld_acquire(bar) < ph * (unsigned)NCTA) { }
                #pragma unroll
                for (int i = 0; i < 8; ++i) st_release(rel + i * 64, ph);
            }
            const unsigned* mr = rel + (cta & 7) * 64;
            while (ld_acquire(mr) < ph) __nanosleep(32);
        }
        __syncthreads();
    }
}

// ---------------- launch ----------------
extern "C" void kernel_launch(void* const* d_in, const int* in_sizes, int n_in,
                              void* d_out, int out_size){
    const float* x    = (const float*)d_in[0];
    const float* W_ih = (const float*)d_in[1];
    const float* W_hh = (const float*)d_in[2];
    const float* b_ih = (const float*)d_in[3];
    const float* b_hh = (const float*)d_in[4];
    const float* Wo   = (const float*)d_in[5];
    const float* bo   = (const float*)d_in[6];
    float* out = (float*)d_out;

    unsigned char* base = nullptr;
    cudaGetSymbolAddress((void**)&base, g_scratch);
    float*    gx   = (float*)(base + OFF_GX);
    __half*   xh   = (__half*)(base + OFF_XH);
    __half*   xl   = (__half*)(base + OFF_XL);
    __half*   wih  = (__half*)(base + OFF_WIH);
    __half*   wil  = (__half*)(base + OFF_WIL);
    __half*   wo   = (__half*)(base + OFF_WO);
    __half*   hsb  = (__half*)(base + OFF_HS);
    float*    bias = (float*)(base + OFF_BIAS);
    float*    hbuf = (float*)(base + OFF_HBUF);
    unsigned* bar  = (unsigned*)(base + OFF_BAR);

    cudaFuncSetAttribute(lstm_rec_kernel,
                         cudaFuncAttributeMaxDynamicSharedMemorySize, REC_SMEM);

    setup_kernel<<<G4 / 256, 256>>>(b_ih, b_hh, bias, bar);
    f2h_split_kernel<<<1024, 256>>>(x,    xh,  xl,  TT * INW);
    f2h_split_kernel<<<1024, 256>>>(W_ih, wih, wil, G4 * INW);
    // Wo: lo residual not needed; dump into gx region, which GEMM #1 below
    // fully overwrites afterwards (same stream => ordered).
    f2h_split_kernel<<<1024, 256>>>(Wo, wo, (__half*)gx, INW * HID);

    dim3 g1(G4 / 128, TT / 128);
    gemm_nt_kernel<0, 0><<<g1, 256>>>(xh, wih, bias, gx, TT, G4, INW);
    gemm_nt_kernel<0, 1><<<g1, 256>>>(xl, wih, bias, gx, TT, G4, INW);
    gemm_nt_kernel<0, 1><<<g1, 256>>>(xh, wil, bias, gx, TT, G4, INW);

    lstm_rec_kernel<<<NCTA, RTHREADS, REC_SMEM>>>(W_hh, gx, hsb, hbuf, bar);

    dim3 g2(INW / 128, TT / 128);
    gemm_nt_kernel<1, 0><<<g2, 256>>>(hsb, wo, bo, out, TT, INW, HID);
}

// round 6
// speedup vs baseline: 2.1731x; 2.1731x over previous
#include <cuda_runtime.h>
#include <cuda_fp16.h>
#include <cuda_bf16.h>
#include <cstdint>
#include <cstddef>

#define TT   4096
#define HID  2048
#define INW  2048
#define G4   (4*HID)

#define NCTA     148
#define HPC      14
#define NROWS    (HPC*4)
#define RTHREADS 448
#define NCOPY    8
#define REC_SMEM (NROWS*HID*2)   // 229376 B fp16 W_hh rows

// ---------------- scratch layout ----------------
#define OFF_GX    ((size_t)0)                            // float [T][4H]
#define OFF_XH    (OFF_GX   + (size_t)TT*G4*4)           // half  [T][I] hi
#define OFF_XL    (OFF_XH   + (size_t)TT*INW*2)          // half  [T][I] lo
#define OFF_WIH   (OFF_XL   + (size_t)TT*INW*2)          // half  [4H][I] hi
#define OFF_WIL   (OFF_WIH  + (size_t)G4*INW*2)          // half  [4H][I] lo
#define OFF_WO    (OFF_WIL  + (size_t)G4*INW*2)          // half  [I][H] hi
#define OFF_HS    (OFF_WO   + (size_t)INW*HID*2)         // half  [T][H]
#define OFF_BIAS  (OFF_HS   + (size_t)TT*HID*2)          // float [4H]
#define OFF_HBUF  (OFF_BIAS + (size_t)G4*4)              // float [2][NCOPY][H]
#define OFF_BAR   (OFF_HBUF + (size_t)2*NCOPY*HID*4)     // counter area
#define SCRATCH_BYTES (OFF_BAR + 4096)

__device__ __align__(256) unsigned char g_scratch[SCRATCH_BYTES];

__device__ __forceinline__ float sigf(float x){ return 1.0f / (1.0f + __expf(-x)); }
__device__ __forceinline__ float tanh_fast(float x){
    float e = __expf(2.0f * x);              // inf-safe: e=inf -> 1; e=0 -> -1
    return 1.0f - 2.0f / (e + 1.0f);
}
__device__ __forceinline__ float2 h2f(unsigned u){
    __half2 h = *reinterpret_cast<__half2*>(&u);
    return __half22float2(h);
}
__device__ __forceinline__ void red_release_add(unsigned* p){
    asm volatile("red.release.gpu.global.add.u32 [%0], 1;" :: "l"(p) : "memory");
}
__device__ __forceinline__ unsigned ld_acquire(const unsigned* p){
    unsigned v;
    asm volatile("ld.acquire.gpu.global.u32 %0, [%1];" : "=r"(v) : "l"(p) : "memory");
    return v;
}

// ---------------- conversion / setup ----------------
__global__ void f2h_split_kernel(const float* __restrict__ in, __half* __restrict__ hi,
                                 __half* __restrict__ lo, int n){
    int i = (blockIdx.x * blockDim.x + threadIdx.x) * 4;
    int stride = gridDim.x * blockDim.x * 4;
    for (; i < n; i += stride){
        float4 v = *(const float4*)(in + i);
        __half h0 = __float2half_rn(v.x), h1 = __float2half_rn(v.y);
        __half h2 = __float2half_rn(v.z), h3 = __float2half_rn(v.w);
        ((__half2*)(hi + i))[0] = __halves2half2(h0, h1);
        ((__half2*)(hi + i))[1] = __halves2half2(h2, h3);
        ((__half2*)(lo + i))[0] = __halves2half2(
            __float2half_rn(v.x - __half2float(h0)), __float2half_rn(v.y - __half2float(h1)));
        ((__half2*)(lo + i))[1] = __halves2half2(
            __float2half_rn(v.z - __half2float(h2)), __float2half_rn(v.w - __half2float(h3)));
    }
}

__global__ void setup_kernel(const float* __restrict__ a, const float* __restrict__ b,
                             float* __restrict__ o, unsigned* __restrict__ bar){
    int i = blockIdx.x * blockDim.x + threadIdx.x;
    if (i < G4) o[i] = a[i] + b[i];
    if (blockIdx.x == 0 && threadIdx.x < 1024) bar[threadIdx.x] = 0u;
}

// ---------------- fp16 NT GEMM (mma.sync, f32 accum) ----------------
__device__ __forceinline__ void cp_async16(void* smem, const void* g){
    unsigned s = (unsigned)__cvta_generic_to_shared(smem);
    asm volatile("cp.async.cg.shared.global [%0], [%1], 16;\n" :: "r"(s), "l"(g));
}
__device__ __forceinline__ void cp_commit(){ asm volatile("cp.async.commit_group;\n"); }
template<int N> __device__ __forceinline__ void cp_wait(){
    asm volatile("cp.async.wait_group %0;\n" :: "n"(N));
}
__device__ __forceinline__ void mma16816(float* c, const unsigned* a, const unsigned* b){
    asm volatile(
        "mma.sync.aligned.m16n8k16.row.col.f32.f16.f16.f32 "
        "{%0,%1,%2,%3}, {%4,%5,%6,%7}, {%8,%9}, {%0,%1,%2,%3};"
        : "+f"(c[0]), "+f"(c[1]), "+f"(c[2]), "+f"(c[3])
        : "r"(a[0]), "r"(a[1]), "r"(a[2]), "r"(a[3]), "r"(b[0]), "r"(b[1]));
}

#define GSTRIDE 40   // halves per smem row: 32 data + 8 pad (80B, 16B aligned)

template<int SIG, int ACC>
__global__ __launch_bounds__(256, 1)
void gemm_nt_kernel(const __half* __restrict__ A, const __half* __restrict__ B,
                    const float* __restrict__ bias, float* __restrict__ C,
                    int M, int N, int K){
    __shared__ __half As[2][128 * GSTRIDE];
    __shared__ __half Bs[2][128 * GSTRIDE];
    const int tid = threadIdx.x, wid = tid >> 5, l = tid & 31;
    const int wm = wid & 1, wn = wid >> 1;            // 2x4 warps, 64x32 warp tile
    const int m0 = blockIdx.y * 128, n0 = blockIdx.x * 128;

    float acc[4][4][4];
    #pragma unroll
    for (int i = 0; i < 4; ++i)
        #pragma unroll
        for (int j = 0; j < 4; ++j)
            #pragma unroll
            for (int q = 0; q < 4; ++q) acc[i][j][q] = 0.0f;

    const int NT = K / 32;
    auto load_stage = [&](int s, int kt){
        #pragma unroll
        for (int i = 0; i < 2; ++i){
            int c = tid + i * 256;
            int r = c >> 2, ch = c & 3;
            cp_async16(&As[s][r * GSTRIDE + ch * 8], A + (size_t)(m0 + r) * K + kt + ch * 8);
            cp_async16(&Bs[s][r * GSTRIDE + ch * 8], B + (size_t)(n0 + r) * K + kt + ch * 8);
        }
        cp_commit();
    };

    load_stage(0, 0);
    for (int t = 0; t < NT; ++t){
        if (t + 1 < NT){ load_stage((t + 1) & 1, (t + 1) * 32); cp_wait<1>(); }
        else           { cp_wait<0>(); }
        __syncthreads();
        const __half* Asb = As[t & 1];
        const __half* Bsb = Bs[t & 1];
        #pragma unroll
        for (int k16 = 0; k16 < 2; ++k16){
            unsigned a[4][4], b[4][2];
            const int cc = k16 * 16 + (l & 3) * 2;
            #pragma unroll
            for (int i = 0; i < 4; ++i){
                int r = wm * 64 + i * 16 + (l >> 2);
                a[i][0] = *(const unsigned*)(Asb + r * GSTRIDE + cc);
                a[i][1] = *(const unsigned*)(Asb + (r + 8) * GSTRIDE + cc);
                a[i][2] = *(const unsigned*)(Asb + r * GSTRIDE + cc + 8);
                a[i][3] = *(const unsigned*)(Asb + (r + 8) * GSTRIDE + cc + 8);
            }
            #pragma unroll
            for (int j = 0; j < 4; ++j){
                int r = wn * 32 + j * 8 + (l >> 2);
                b[j][0] = *(const unsigned*)(Bsb + r * GSTRIDE + cc);
                b[j][1] = *(const unsigned*)(Bsb + r * GSTRIDE + cc + 8);
            }
            #pragma unroll
            for (int i = 0; i < 4; ++i)
                #pragma unroll
                for (int j = 0; j < 4; ++j)
                    mma16816(acc[i][j], a[i], b[j]);
        }
        __syncthreads();
    }

    #pragma unroll
    for (int i = 0; i < 4; ++i){
        #pragma unroll
        for (int j = 0; j < 4; ++j){
            int rm = m0 + wm * 64 + i * 16 + (l >> 2);
            int cn = n0 + wn * 32 + j * 8 + (l & 3) * 2;
            float2* p0 = (float2*)(C + (size_t)rm * N + cn);
            float2* p1 = (float2*)(C + (size_t)(rm + 8) * N + cn);
            float v0, v1, v2, v3;
            if (ACC){
                float2 o0 = *p0, o1 = *p1;
                v0 = acc[i][j][0] + o0.x; v1 = acc[i][j][1] + o0.y;
                v2 = acc[i][j][2] + o1.x; v3 = acc[i][j][3] + o1.y;
            } else {
                float b0 = bias[cn], b1 = bias[cn + 1];
                v0 = acc[i][j][0] + b0; v1 = acc[i][j][1] + b1;
                v2 = acc[i][j][2] + b0; v3 = acc[i][j][3] + b1;
                if (SIG){ v0 = sigf(v0); v1 = sigf(v1); v2 = sigf(v2); v3 = sigf(v3); }
            }
            *p0 = make_float2(v0, v1);
            *p1 = make_float2(v2, v3);
        }
    }
}

// ---------------- persistent LSTM recurrence ----------------
// 148 CTAs (1/SM). CTA c owns h-elements [c*14, c*14+14); their 56 W_hh rows
// live in SMEM as fp16 (224KB). One warp per h-element, fp32 accumulate.
// h is kept in global in NCOPY=8 replicas (8KB apart -> spread over L2 slices);
// each warp reads replica (cta+w)&7 with fully-coalesced 16B loads; lanes 0-7
// write the 8 replicas. Direct-spin grid barrier (release-add / acquire-poll).
__global__ __launch_bounds__(RTHREADS, 1)
void lstm_rec_kernel(const float* __restrict__ Whh, const float* __restrict__ gx,
                     __half* __restrict__ hs, float* __restrict__ hbuf,
                     unsigned* __restrict__ bar){
    extern __shared__ uint2 smW2[];                   // [56][512] uint2 = 2048 fp16/row
    unsigned* smw32 = (unsigned*)smW2;
    const int tid = threadIdx.x;
    const int w = tid >> 5, l = tid & 31;
    const int cta = blockIdx.x;

    // load + convert this CTA's W_hh rows to fp16 in SMEM (row-major halfs)
    for (int idx = tid; idx < NROWS * 1024; idx += RTHREADS){
        int sr = idx >> 10, wc = idx & 1023;
        int e = cta * HPC + (sr >> 2);
        int gate = sr & 3;
        unsigned val = 0u;
        if (e < HID){
            const float2 f2 = *(const float2*)(Whh + (size_t)(gate * HID + e) * HID + 2 * wc);
            unsigned lo = (unsigned)__half_as_ushort(__float2half_rn(f2.x));
            unsigned hi = (unsigned)__half_as_ushort(__float2half_rn(f2.y));
            val = (hi << 16) | lo;
        }
        smw32[sr * 1024 + wc] = val;
    }
    // zero all replicas of h buffer 0
    if (tid < HPC){
        int e = cta * HPC + tid;
        if (e < HID){
            #pragma unroll
            for (int k = 0; k < NCOPY; ++k) hbuf[k * HID + e] = 0.0f;
        }
    }
    __syncthreads();
    if (tid == 0){
        red_release_add(bar);
        while (ld_acquire(bar) < (unsigned)NCTA) { }
    }
    __syncthreads();

    const int e = cta * HPC + w;
    const bool active = (e < HID);
    const int w4 = w * 4;
    const int mycopy = (cta + w) & (NCOPY - 1);
    float c = 0.0f;

    #pragma unroll 1
    for (int t = 0; t < TT; ++t){
        const float4* hr4 = (const float4*)(hbuf + ((size_t)(t & 1) * NCOPY + mycopy) * HID);
        float* hwb = hbuf + (size_t)((t + 1) & 1) * NCOPY * HID;

        float gx0 = 0.f, gx1 = 0.f, gx2 = 0.f, gx3 = 0.f;
        if (active){
            const float* gp = gx + (size_t)t * G4 + e;
            gx0 = __ldcg(gp);
            gx1 = __ldcg(gp + HID);
            gx2 = __ldcg(gp + 2 * HID);
            gx3 = __ldcg(gp + 3 * HID);
        }

        // fully coalesced: lane l reads float4 index l+32j (contiguous 512B/instr)
        float4 hv[16];
        #pragma unroll
        for (int j = 0; j < 16; ++j)
            hv[j] = __ldcg(hr4 + l + 32 * j);

        float acc0 = 0.f, acc1 = 0.f, acc2 = 0.f, acc3 = 0.f;
        #pragma unroll
        for (int j = 0; j < 16; ++j){
            float4 h4 = hv[j];
            {
                uint2 wv = smW2[(w4 + 0) * 512 + l + 32 * j];
                float2 w0 = h2f(wv.x), w1 = h2f(wv.y);
                acc0 += w0.x * h4.x; acc0 += w0.y * h4.y;
                acc0 += w1.x * h4.z; acc0 += w1.y * h4.w;
            }
            {
                uint2 wv = smW2[(w4 + 1) * 512 + l + 32 * j];
                float2 w0 = h2f(wv.x), w1 = h2f(wv.y);
                acc1 += w0.x * h4.x; acc1 += w0.y * h4.y;
                acc1 += w1.x * h4.z; acc1 += w1.y * h4.w;
            }
            {
                uint2 wv = smW2[(w4 + 2) * 512 + l + 32 * j];
                float2 w0 = h2f(wv.x), w1 = h2f(wv.y);
                acc2 += w0.x * h4.x; acc2 += w0.y * h4.y;
                acc2 += w1.x * h4.z; acc2 += w1.y * h4.w;
            }
            {
                uint2 wv = smW2[(w4 + 3) * 512 + l + 32 * j];
                float2 w0 = h2f(wv.x), w1 = h2f(wv.y);
                acc3 += w0.x * h4.x; acc3 += w0.y * h4.y;
                acc3 += w1.x * h4.z; acc3 += w1.y * h4.w;
            }
        }
        #pragma unroll
        for (int off = 16; off; off >>= 1){
            acc0 += __shfl_xor_sync(0xffffffffu, acc0, off);
            acc1 += __shfl_xor_sync(0xffffffffu, acc1, off);
            acc2 += __shfl_xor_sync(0xffffffffu, acc2, off);
            acc3 += __shfl_xor_sync(0xffffffffu, acc3, off);
        }

        // all lanes compute identical gate math; lanes 0-7 store the replicas
        float ig = sigf(acc0 + gx0);
        float fg = sigf(acc1 + gx1);
        float gt = tanh_fast(acc2 + gx2);
        float og = sigf(acc3 + gx3);
        c = fg * c + ig * gt;
        float hn = og * tanh_fast(c);
        if (active){
            if (l < NCOPY) __stcg(&hwb[l * HID + e], hn);
            if (l == 0)    __stcg(&hs[(size_t)t * HID + e], __float2half(hn));
        }

        // grid barrier: release-arrive, every tid0 polls the counter directly
        __syncthreads();
        if (tid == 0){
            red_release_add(bar);
            const unsigned target = (unsigned)(t + 2) * (unsigned)NCTA;
            while (ld_acquire(bar) < target) { }
        }
        __syncthreads();
    }
}

// ---------------- launch ----------------
extern "C" void kernel_launch(void* const* d_in, const int* in_sizes, int n_in,
                              void* d_out, int out_size){
    const float* x    = (const float*)d_in[0];
    const float* W_ih = (const float*)d_in[1];
    const float* W_hh = (const float*)d_in[2];
    const float* b_ih = (const float*)d_in[3];
    const float* b_hh = (const float*)d_in[4];
    const float* Wo   = (const float*)d_in[5];
    const float* bo   = (const float*)d_in[6];
    float* out = (float*)d_out;

    unsigned char* base = nullptr;
    cudaGetSymbolAddress((void**)&base, g_scratch);
    float*    gx   = (float*)(base + OFF_GX);
    __half*   xh   = (__half*)(base + OFF_XH);
    __half*   xl   = (__half*)(base + OFF_XL);
    __half*   wih  = (__half*)(base + OFF_WIH);
    __half*   wil  = (__half*)(base + OFF_WIL);
    __half*   wo   = (__half*)(base + OFF_WO);
    __half*   hsb  = (__half*)(base + OFF_HS);
    float*    bias = (float*)(base + OFF_BIAS);
    float*    hbuf = (float*)(base + OFF_HBUF);
    unsigned* bar  = (unsigned*)(base + OFF_BAR);

    cudaFuncSetAttribute(lstm_rec_kernel,
                         cudaFuncAttributeMaxDynamicSharedMemorySize, REC_SMEM);

    setup_kernel<<<G4 / 256, 256>>>(b_ih, b_hh, bias, bar);
    f2h_split_kernel<<<1024, 256>>>(x,    xh,  xl,  TT * INW);
    f2h_split_kernel<<<1024, 256>>>(W_ih, wih, wil, G4 * INW);
    // Wo: lo residual not needed; dump into gx region, which GEMM #1 below
    // fully overwrites afterwards (same stream => ordered).
    f2h_split_kernel<<<1024, 256>>>(Wo, wo, (__half*)gx, INW * HID);

    dim3 g1(G4 / 128, TT / 128);
    gemm_nt_kernel<0, 0><<<g1, 256>>>(xh, wih, bias, gx, TT, G4, INW);
    gemm_nt_kernel<0, 1><<<g1, 256>>>(xl, wih, bias, gx, TT, G4, INW);
    gemm_nt_kernel<0, 1><<<g1, 256>>>(xh, wil, bias, gx, TT, G4, INW);

    lstm_rec_kernel<<<NCTA, RTHREADS, REC_SMEM>>>(W_hh, gx, hsb, hbuf, bar);

    dim3 g2(INW / 128, TT / 128);
    gemm_nt_kernel<1, 0><<<g2, 256>>>(hsb, wo, bo, out, TT, INW, HID);
}

// round 8
// speedup vs baseline: 2.4128x; 1.1103x over previous
#include <cuda_runtime.h>
#include <cuda_fp16.h>
#include <cuda_bf16.h>
#include <cstdint>
#include <cstddef>

#define TT   4096
#define HID  2048
#define INW  2048
#define G4   (4*HID)

#define NCTA     148
#define HPC      14
#define NROWS    (HPC*4)
#define RTHREADS 224
#define NCOPY    8
#define REC_SMEM (NROWS*HID*2)   // 229376 B fp16 W_hh rows

// ---------------- scratch layout ----------------
#define OFF_GX    ((size_t)0)                            // float [T][4H]
#define OFF_XH    (OFF_GX   + (size_t)TT*G4*4)           // half  [T][I] hi
#define OFF_XL    (OFF_XH   + (size_t)TT*INW*2)          // half  [T][I] lo
#define OFF_WIH   (OFF_XL   + (size_t)TT*INW*2)          // half  [4H][I] hi
#define OFF_WIL   (OFF_WIH  + (size_t)G4*INW*2)          // half  [4H][I] lo
#define OFF_WO    (OFF_WIL  + (size_t)G4*INW*2)          // half  [I][H] hi
#define OFF_HS    (OFF_WO   + (size_t)INW*HID*2)         // half  [T][H]
#define OFF_BIAS  (OFF_HS   + (size_t)TT*HID*2)          // float [4H]
#define OFF_HBUF  (OFF_BIAS + (size_t)G4*4)              // float [2][NCOPY][H]
#define OFF_BAR   (OFF_HBUF + (size_t)2*NCOPY*HID*4)     // counter area
#define SCRATCH_BYTES (OFF_BAR + 4096)

__device__ __align__(256) unsigned char g_scratch[SCRATCH_BYTES];

__device__ __forceinline__ float sigf(float x){ return 1.0f / (1.0f + __expf(-x)); }
__device__ __forceinline__ float tanh_fast(float x){
    float e = __expf(2.0f * x);              // inf-safe: e=inf -> 1; e=0 -> -1
    return 1.0f - 2.0f / (e + 1.0f);
}
__device__ __forceinline__ void red_release_add(unsigned* p){
    asm volatile("red.release.gpu.global.add.u32 [%0], 1;" :: "l"(p) : "memory");
}
__device__ __forceinline__ unsigned ld_acquire(const unsigned* p){
    unsigned v;
    asm volatile("ld.acquire.gpu.global.u32 %0, [%1];" : "=r"(v) : "l"(p) : "memory");
    return v;
}
__device__ __forceinline__ __half2 u2h2(unsigned u){
    __half2 h; *reinterpret_cast<unsigned*>(&h) = u; return h;
}

// ---------------- conversion / setup ----------------
__global__ void f2h_split_kernel(const float* __restrict__ in, __half* __restrict__ hi,
                                 __half* __restrict__ lo, int n){
    int i = (blockIdx.x * blockDim.x + threadIdx.x) * 4;
    int stride = gridDim.x * blockDim.x * 4;
    for (; i < n; i += stride){
        float4 v = *(const float4*)(in + i);
        __half h0 = __float2half_rn(v.x), h1 = __float2half_rn(v.y);
        __half h2 = __float2half_rn(v.z), h3 = __float2half_rn(v.w);
        ((__half2*)(hi + i))[0] = __halves2half2(h0, h1);
        ((__half2*)(hi + i))[1] = __halves2half2(h2, h3);
        ((__half2*)(lo + i))[0] = __halves2half2(
            __float2half_rn(v.x - __half2float(h0)), __float2half_rn(v.y - __half2float(h1)));
        ((__half2*)(lo + i))[1] = __halves2half2(
            __float2half_rn(v.z - __half2float(h2)), __float2half_rn(v.w - __half2float(h3)));
    }
}

__global__ void setup_kernel(const float* __restrict__ a, const float* __restrict__ b,
                             float* __restrict__ o, unsigned* __restrict__ bar){
    int i = blockIdx.x * blockDim.x + threadIdx.x;
    if (i < G4) o[i] = a[i] + b[i];
    if (blockIdx.x == 0 && threadIdx.x < 1024) bar[threadIdx.x] = 0u;
}

// ---------------- fp16 NT GEMM (mma.sync, f32 accum) ----------------
__device__ __forceinline__ void cp_async16(void* smem, const void* g){
    unsigned s = (unsigned)__cvta_generic_to_shared(smem);
    asm volatile("cp.async.cg.shared.global [%0], [%1], 16;\n" :: "r"(s), "l"(g));
}
__device__ __forceinline__ void cp_commit(){ asm volatile("cp.async.commit_group;\n"); }
template<int N> __device__ __forceinline__ void cp_wait(){
    asm volatile("cp.async.wait_group %0;\n" :: "n"(N));
}
__device__ __forceinline__ void mma16816(float* c, const unsigned* a, const unsigned* b){
    asm volatile(
        "mma.sync.aligned.m16n8k16.row.col.f32.f16.f16.f32 "
        "{%0,%1,%2,%3}, {%4,%5,%6,%7}, {%8,%9}, {%0,%1,%2,%3};"
        : "+f"(c[0]), "+f"(c[1]), "+f"(c[2]), "+f"(c[3])
        : "r"(a[0]), "r"(a[1]), "r"(a[2]), "r"(a[3]), "r"(b[0]), "r"(b[1]));
}

#define GSTRIDE 40   // halves per smem row: 32 data + 8 pad (80B, 16B aligned)

template<int SIG, int ACC>
__global__ __launch_bounds__(256, 1)
void gemm_nt_kernel(const __half* __restrict__ A, const __half* __restrict__ B,
                    const float* __restrict__ bias, float* __restrict__ C,
                    int M, int N, int K){
    __shared__ __half As[2][128 * GSTRIDE];
    __shared__ __half Bs[2][128 * GSTRIDE];
    const int tid = threadIdx.x, wid = tid >> 5, l = tid & 31;
    const int wm = wid & 1, wn = wid >> 1;            // 2x4 warps, 64x32 warp tile
    const int m0 = blockIdx.y * 128, n0 = blockIdx.x * 128;

    float acc[4][4][4];
    #pragma unroll
    for (int i = 0; i < 4; ++i)
        #pragma unroll
        for (int j = 0; j < 4; ++j)
            #pragma unroll
            for (int q = 0; q < 4; ++q) acc[i][j][q] = 0.0f;

    const int NT = K / 32;
    auto load_stage = [&](int s, int kt){
        #pragma unroll
        for (int i = 0; i < 2; ++i){
            int c = tid + i * 256;
            int r = c >> 2, ch = c & 3;
            cp_async16(&As[s][r * GSTRIDE + ch * 8], A + (size_t)(m0 + r) * K + kt + ch * 8);
            cp_async16(&Bs[s][r * GSTRIDE + ch * 8], B + (size_t)(n0 + r) * K + kt + ch * 8);
        }
        cp_commit();
    };

    load_stage(0, 0);
    for (int t = 0; t < NT; ++t){
        if (t + 1 < NT){ load_stage((t + 1) & 1, (t + 1) * 32); cp_wait<1>(); }
        else           { cp_wait<0>(); }
        __syncthreads();
        const __half* Asb = As[t & 1];
        const __half* Bsb = Bs[t & 1];
        #pragma unroll
        for (int k16 = 0; k16 < 2; ++k16){
            unsigned a[4][4], b[4][2];
            const int cc = k16 * 16 + (l & 3) * 2;
            #pragma unroll
            for (int i = 0; i < 4; ++i){
                int r = wm * 64 + i * 16 + (l >> 2);
                a[i][0] = *(const unsigned*)(Asb + r * GSTRIDE + cc);
                a[i][1] = *(const unsigned*)(Asb + (r + 8) * GSTRIDE + cc);
                a[i][2] = *(const unsigned*)(Asb + r * GSTRIDE + cc + 8);
                a[i][3] = *(const unsigned*)(Asb + (r + 8) * GSTRIDE + cc + 8);
            }
            #pragma unroll
            for (int j = 0; j < 4; ++j){
                int r = wn * 32 + j * 8 + (l >> 2);
                b[j][0] = *(const unsigned*)(Bsb + r * GSTRIDE + cc);
                b[j][1] = *(const unsigned*)(Bsb + r * GSTRIDE + cc + 8);
            }
            #pragma unroll
            for (int i = 0; i < 4; ++i)
                #pragma unroll
                for (int j = 0; j < 4; ++j)
                    mma16816(acc[i][j], a[i], b[j]);
        }
        __syncthreads();
    }

    #pragma unroll
    for (int i = 0; i < 4; ++i){
        #pragma unroll
        for (int j = 0; j < 4; ++j){
            int rm = m0 + wm * 64 + i * 16 + (l >> 2);
            int cn = n0 + wn * 32 + j * 8 + (l & 3) * 2;
            float2* p0 = (float2*)(C + (size_t)rm * N + cn);
            float2* p1 = (float2*)(C + (size_t)(rm + 8) * N + cn);
            float v0, v1, v2, v3;
            if (ACC){
                float2 o0 = *p0, o1 = *p1;
                v0 = acc[i][j][0] + o0.x; v1 = acc[i][j][1] + o0.y;
                v2 = acc[i][j][2] + o1.x; v3 = acc[i][j][3] + o1.y;
            } else {
                float b0 = bias[cn], b1 = bias[cn + 1];
                v0 = acc[i][j][0] + b0; v1 = acc[i][j][1] + b1;
                v2 = acc[i][j][2] + b0; v3 = acc[i][j][3] + b1;
                if (SIG){ v0 = sigf(v0); v1 = sigf(v1); v2 = sigf(v2); v3 = sigf(v3); }
            }
            *p0 = make_float2(v0, v1);
            *p1 = make_float2(v2, v3);
        }
    }
}

// ---------------- persistent LSTM recurrence ----------------
// 148 CTAs (1/SM), 224 threads = 7 warps. Warp w owns 2 h-elements
// (e0 = cta*14 + 2w, e1 = e0+1) -> 8 W_hh rows in SMEM (fp16, 224KB total).
// Dot products via HFMA2 with half2 accumulators flushed to fp32 every 4
// j-iterations (kills the F2F bottleneck). h in global fp32, 8 replicas.
__global__ __launch_bounds__(RTHREADS, 1)
void lstm_rec_kernel(const float* __restrict__ Whh, const float* __restrict__ gx,
                     __half* __restrict__ hs, float* __restrict__ hbuf,
                     unsigned* __restrict__ bar){
    extern __shared__ uint2 smW2[];                   // [56][512] uint2 = 2048 fp16/row
    unsigned* smw32 = (unsigned*)smW2;
    const int tid = threadIdx.x;
    const int w = tid >> 5, l = tid & 31;
    const int cta = blockIdx.x;

    // load + convert this CTA's W_hh rows to fp16 in SMEM (row sr = local_e*4+gate)
    for (int idx = tid; idx < NROWS * 1024; idx += RTHREADS){
        int sr = idx >> 10, wc = idx & 1023;
        int e = cta * HPC + (sr >> 2);
        int gate = sr & 3;
        unsigned val = 0u;
        if (e < HID){
            const float2 f2 = *(const float2*)(Whh + (size_t)(gate * HID + e) * HID + 2 * wc);
            unsigned lo = (unsigned)__half_as_ushort(__float2half_rn(f2.x));
            unsigned hi = (unsigned)__half_as_ushort(__float2half_rn(f2.y));
            val = (hi << 16) | lo;
        }
        smw32[sr * 1024 + wc] = val;
    }
    // zero all replicas of h buffer 0
    if (tid < HPC){
        int e = cta * HPC + tid;
        if (e < HID){
            #pragma unroll
            for (int k = 0; k < NCOPY; ++k) hbuf[k * HID + e] = 0.0f;
        }
    }
    __syncthreads();
    if (tid == 0){
        red_release_add(bar);
        while (ld_acquire(bar) < (unsigned)NCTA) { }
    }
    __syncthreads();

    const int e0 = cta * HPC + 2 * w;
    const int e1 = e0 + 1;
    const bool a0 = (e0 < HID);
    const bool a1 = (e1 < HID);
    const int rowbase = w * 8;                        // rows rowbase..rowbase+7
    const int mycopy = (cta + w) & (NCOPY - 1);
    float c0 = 0.0f, c1 = 0.0f;

    #pragma unroll 1
    for (int t = 0; t < TT; ++t){
        const float4* hr4 = (const float4*)(hbuf + ((size_t)(t & 1) * NCOPY + mycopy) * HID);
        float* hwb = hbuf + (size_t)((t + 1) & 1) * NCOPY * HID;

        // gate input projections for both elements (uniform per-warp loads)
        float gxe[8];
        #pragma unroll
        for (int g = 0; g < 4; ++g){
            gxe[g]     = a0 ? __ldcg(gx + (size_t)t * G4 + g * HID + e0) : 0.f;
            gxe[4 + g] = a1 ? __ldcg(gx + (size_t)t * G4 + g * HID + e1) : 0.f;
        }

        // coalesced h load: lane l reads float4 index l+32j (contiguous 512B)
        float4 hv[16];
        #pragma unroll
        for (int j = 0; j < 16; ++j)
            hv[j] = __ldcg(hr4 + l + 32 * j);

        // convert h to half2 pairs once (F2FP packed cvt, cheap)
        __half2 hh[32];
        #pragma unroll
        for (int j = 0; j < 16; ++j){
            hh[2 * j]     = __floats2half2_rn(hv[j].x, hv[j].y);
            hh[2 * j + 1] = __floats2half2_rn(hv[j].z, hv[j].w);
        }

        float acc[8] = {0.f,0.f,0.f,0.f,0.f,0.f,0.f,0.f};
        #pragma unroll
        for (int ch = 0; ch < 4; ++ch){
            __half2 ha[8];
            #pragma unroll
            for (int r = 0; r < 8; ++r) ha[r] = __halves2half2(__ushort_as_half(0), __ushort_as_half(0));
            #pragma unroll
            for (int jj = 0; jj < 4; ++jj){
                const int j = ch * 4 + jj;
                const __half2 h01 = hh[2 * j], h23 = hh[2 * j + 1];
                #pragma unroll
                for (int r = 0; r < 8; ++r){
                    uint2 wv = smW2[(rowbase + r) * 512 + l + 32 * j];
                    ha[r] = __hfma2(u2h2(wv.x), h01, ha[r]);
                    ha[r] = __hfma2(u2h2(wv.y), h23, ha[r]);
                }
            }
            #pragma unroll
            for (int r = 0; r < 8; ++r){
                float2 f2 = __half22float2(ha[r]);
                acc[r] += f2.x + f2.y;
            }
        }
        #pragma unroll
        for (int off = 16; off; off >>= 1){
            #pragma unroll
            for (int r = 0; r < 8; ++r)
                acc[r] += __shfl_xor_sync(0xffffffffu, acc[r], off);
        }

        // gate math for both elements (all lanes redundantly; uniform values)
        float ig0 = sigf(acc[0] + gxe[0]);
        float fg0 = sigf(acc[1] + gxe[1]);
        float gt0 = tanh_fast(acc[2] + gxe[2]);
        float og0 = sigf(acc[3] + gxe[3]);
        c0 = fg0 * c0 + ig0 * gt0;
        float hn0 = og0 * tanh_fast(c0);

        float ig1 = sigf(acc[4] + gxe[4]);
        float fg1 = sigf(acc[5] + gxe[5]);
        float gt1 = tanh_fast(acc[6] + gxe[6]);
        float og1 = sigf(acc[7] + gxe[7]);
        c1 = fg1 * c1 + ig1 * gt1;
        float hn1 = og1 * tanh_fast(c1);

        if (a0 && l < NCOPY)                __stcg(&hwb[l * HID + e0], hn0);
        if (a1 && l >= NCOPY && l < 2*NCOPY) __stcg(&hwb[(l - NCOPY) * HID + e1], hn1);
        if (a0 && l == 0) __stcg(&hs[(size_t)t * HID + e0], __float2half(hn0));
        if (a1 && l == 1) __stcg(&hs[(size_t)t * HID + e1], __float2half(hn1));

        // grid barrier: release-arrive, every tid0 polls the counter directly
        __syncthreads();
        if (tid == 0){
            red_release_add(bar);
            const unsigned target = (unsigned)(t + 2) * (unsigned)NCTA;
            while (ld_acquire(bar) < target) { }
        }
        __syncthreads();
    }
}

// ---------------- launch ----------------
extern "C" void kernel_launch(void* const* d_in, const int* in_sizes, int n_in,
                              void* d_out, int out_size){
    const float* x    = (const float*)d_in[0];
    const float* W_ih = (const float*)d_in[1];
    const float* W_hh = (const float*)d_in[2];
    const float* b_ih = (const float*)d_in[3];
    const float* b_hh = (const float*)d_in[4];
    const float* Wo   = (const float*)d_in[5];
    const float* bo   = (const float*)d_in[6];
    float* out = (float*)d_out;

    unsigned char* base = nullptr;
    cudaGetSymbolAddress((void**)&base, g_scratch);
    float*    gx   = (float*)(base + OFF_GX);
    __half*   xh   = (__half*)(base + OFF_XH);
    __half*   xl   = (__half*)(base + OFF_XL);
    __half*   wih  = (__half*)(base + OFF_WIH);
    __half*   wil  = (__half*)(base + OFF_WIL);
    __half*   wo   = (__half*)(base + OFF_WO);
    __half*   hsb  = (__half*)(base + OFF_HS);
    float*    bias = (float*)(base + OFF_BIAS);
    float*    hbuf = (float*)(base + OFF_HBUF);
    unsigned* bar  = (unsigned*)(base + OFF_BAR);

    cudaFuncSetAttribute(lstm_rec_kernel,
                         cudaFuncAttributeMaxDynamicSharedMemorySize, REC_SMEM);

    setup_kernel<<<G4 / 256, 256>>>(b_ih, b_hh, bias, bar);
    f2h_split_kernel<<<1024, 256>>>(x,    xh,  xl,  TT * INW);
    f2h_split_kernel<<<1024, 256>>>(W_ih, wih, wil, G4 * INW);
    // Wo: lo residual not needed; dump into gx region, which GEMM #1 below
    // fully overwrites afterwards (same stream => ordered).
    f2h_split_kernel<<<1024, 256>>>(Wo, wo, (__half*)gx, INW * HID);

    dim3 g1(G4 / 128, TT / 128);
    gemm_nt_kernel<0, 0><<<g1, 256>>>(xh, wih, bias, gx, TT, G4, INW);
    gemm_nt_kernel<0, 1><<<g1, 256>>>(xl, wih, bias, gx, TT, G4, INW);
    gemm_nt_kernel<0, 1><<<g1, 256>>>(xh, wil, bias, gx, TT, G4, INW);

    lstm_rec_kernel<<<NCTA, RTHREADS, REC_SMEM>>>(W_hh, gx, hsb, hbuf, bar);

    dim3 g2(INW / 128, TT / 128);
    gemm_nt_kernel<1, 0><<<g2, 256>>>(hsb, wo, bo, out, TT, INW, HID);
}

// round 11
// speedup vs baseline: 2.5075x; 1.0392x over previous
#include <cuda_runtime.h>
#include <cuda_fp16.h>
#include <cuda_bf16.h>
#include <cstdint>
#include <cstddef>

#define TT   4096
#define HID  2048
#define INW  2048
#define G4   (4*HID)

#define NCTA     148
#define HPC      14
#define NROWS    (HPC*4)
#define RTHREADS 224
#define NCOPY    8
#define REC_SMEM (NROWS*HID*2)   // 229376 B fp16 W_hh rows

// ---------------- scratch layout ----------------
#define OFF_GX    ((size_t)0)                            // float [T][4H]
#define OFF_XH    (OFF_GX   + (size_t)TT*G4*4)           // half  [T][I] hi
#define OFF_XL    (OFF_XH   + (size_t)TT*INW*2)          // half  [T][I] lo
#define OFF_WIH   (OFF_XL   + (size_t)TT*INW*2)          // half  [4H][I] hi
#define OFF_WIL   (OFF_WIH  + (size_t)G4*INW*2)          // half  [4H][I] lo
#define OFF_WO    (OFF_WIL  + (size_t)G4*INW*2)          // half  [I][H] hi
#define OFF_HS    (OFF_WO   + (size_t)INW*HID*2)         // half  [T][H]
#define OFF_BIAS  (OFF_HS   + (size_t)TT*HID*2)          // float [4H]
#define OFF_HBUF  (OFF_BIAS + (size_t)G4*4)              // float [2][NCOPY][H]
#define OFF_BAR   (OFF_HBUF + (size_t)2*NCOPY*HID*4)     // counter area
#define SCRATCH_BYTES (OFF_BAR + 4096)

__device__ __align__(256) unsigned char g_scratch[SCRATCH_BYTES];

__device__ __forceinline__ float sigf(float x){ return 1.0f / (1.0f + __expf(-x)); }
__device__ __forceinline__ float tanh_fast(float x){
    float e = __expf(2.0f * x);              // inf-safe: e=inf -> 1; e=0 -> -1
    return 1.0f - 2.0f / (e + 1.0f);
}
__device__ __forceinline__ void red_release_add(unsigned* p){
    asm volatile("red.release.gpu.global.add.u32 [%0], 1;" :: "l"(p) : "memory");
}
__device__ __forceinline__ unsigned ld_acquire(const unsigned* p){
    unsigned v;
    asm volatile("ld.acquire.gpu.global.u32 %0, [%1];" : "=r"(v) : "l"(p) : "memory");
    return v;
}
__device__ __forceinline__ __half2 u2h2(unsigned u){
    __half2 h; *reinterpret_cast<unsigned*>(&h) = u; return h;
}

// ---------------- conversion / setup ----------------
__global__ void f2h_split_kernel(const float* __restrict__ in, __half* __restrict__ hi,
                                 __half* __restrict__ lo, int n){
    int i = (blockIdx.x * blockDim.x + threadIdx.x) * 4;
    int stride = gridDim.x * blockDim.x * 4;
    for (; i < n; i += stride){
        float4 v = *(const float4*)(in + i);
        __half h0 = __float2half_rn(v.x), h1 = __float2half_rn(v.y);
        __half h2 = __float2half_rn(v.z), h3 = __float2half_rn(v.w);
        ((__half2*)(hi + i))[0] = __halves2half2(h0, h1);
        ((__half2*)(hi + i))[1] = __halves2half2(h2, h3);
        ((__half2*)(lo + i))[0] = __halves2half2(
            __float2half_rn(v.x - __half2float(h0)), __float2half_rn(v.y - __half2float(h1)));
        ((__half2*)(lo + i))[1] = __halves2half2(
            __float2half_rn(v.z - __half2float(h2)), __float2half_rn(v.w - __half2float(h3)));
    }
}

__global__ void setup_kernel(const float* __restrict__ a, const float* __restrict__ b,
                             float* __restrict__ o, unsigned* __restrict__ bar){
    int i = blockIdx.x * blockDim.x + threadIdx.x;
    if (i < G4) o[i] = a[i] + b[i];
    if (blockIdx.x == 0 && threadIdx.x < 1024) bar[threadIdx.x] = 0u;
}

// ---------------- fp16 NT GEMM (mma.sync, f32 accum) ----------------
__device__ __forceinline__ void cp_async16(void* smem, const void* g){
    unsigned s = (unsigned)__cvta_generic_to_shared(smem);
    asm volatile("cp.async.cg.shared.global [%0], [%1], 16;\n" :: "r"(s), "l"(g));
}
__device__ __forceinline__ void cp_commit(){ asm volatile("cp.async.commit_group;\n"); }
template<int N> __device__ __forceinline__ void cp_wait(){
    asm volatile("cp.async.wait_group %0;\n" :: "n"(N));
}
__device__ __forceinline__ void mma16816(float* c, const unsigned* a, const unsigned* b){
    asm volatile(
        "mma.sync.aligned.m16n8k16.row.col.f32.f16.f16.f32 "
        "{%0,%1,%2,%3}, {%4,%5,%6,%7}, {%8,%9}, {%0,%1,%2,%3};"
        : "+f"(c[0]), "+f"(c[1]), "+f"(c[2]), "+f"(c[3])
        : "r"(a[0]), "r"(a[1]), "r"(a[2]), "r"(a[3]), "r"(b[0]), "r"(b[1]));
}

#define GSTRIDE 40   // halves per smem row: 32 data + 8 pad (80B, 16B aligned)

template<int SIG, int ACC>
__global__ __launch_bounds__(256, 1)
void gemm_nt_kernel(const __half* __restrict__ A, const __half* __restrict__ B,
                    const float* __restrict__ bias, float* __restrict__ C,
                    int M, int N, int K){
    __shared__ __half As[2][128 * GSTRIDE];
    __shared__ __half Bs[2][128 * GSTRIDE];
    const int tid = threadIdx.x, wid = tid >> 5, l = tid & 31;
    const int wm = wid & 1, wn = wid >> 1;            // 2x4 warps, 64x32 warp tile
    const int m0 = blockIdx.y * 128, n0 = blockIdx.x * 128;

    float acc[4][4][4];
    #pragma unroll
    for (int i = 0; i < 4; ++i)
        #pragma unroll
        for (int j = 0; j < 4; ++j)
            #pragma unroll
            for (int q = 0; q < 4; ++q) acc[i][j][q] = 0.0f;

    const int NT = K / 32;
    auto load_stage = [&](int s, int kt){
        #pragma unroll
        for (int i = 0; i < 2; ++i){
            int c = tid + i * 256;
            int r = c >> 2, ch = c & 3;
            cp_async16(&As[s][r * GSTRIDE + ch * 8], A + (size_t)(m0 + r) * K + kt + ch * 8);
            cp_async16(&Bs[s][r * GSTRIDE + ch * 8], B + (size_t)(n0 + r) * K + kt + ch * 8);
        }
        cp_commit();
    };

    load_stage(0, 0);
    for (int t = 0; t < NT; ++t){
        if (t + 1 < NT){ load_stage((t + 1) & 1, (t + 1) * 32); cp_wait<1>(); }
        else           { cp_wait<0>(); }
        __syncthreads();
        const __half* Asb = As[t & 1];
        const __half* Bsb = Bs[t & 1];
        #pragma unroll
        for (int k16 = 0; k16 < 2; ++k16){
            unsigned a[4][4], b[4][2];
            const int cc = k16 * 16 + (l & 3) * 2;
            #pragma unroll
            for (int i = 0; i < 4; ++i){
                int r = wm * 64 + i * 16 + (l >> 2);
                a[i][0] = *(const unsigned*)(Asb + r * GSTRIDE + cc);
                a[i][1] = *(const unsigned*)(Asb + (r + 8) * GSTRIDE + cc);
                a[i][2] = *(const unsigned*)(Asb + r * GSTRIDE + cc + 8);
                a[i][3] = *(const unsigned*)(Asb + (r + 8) * GSTRIDE + cc + 8);
            }
            #pragma unroll
            for (int j = 0; j < 4; ++j){
                int r = wn * 32 + j * 8 + (l >> 2);
                b[j][0] = *(const unsigned*)(Bsb + r * GSTRIDE + cc);
                b[j][1] = *(const unsigned*)(Bsb + r * GSTRIDE + cc + 8);
            }
            #pragma unroll
            for (int i = 0; i < 4; ++i)
                #pragma unroll
                for (int j = 0; j < 4; ++j)
                    mma16816(acc[i][j], a[i], b[j]);
        }
        __syncthreads();
    }

    #pragma unroll
    for (int i = 0; i < 4; ++i){
        #pragma unroll
        for (int j = 0; j < 4; ++j){
            int rm = m0 + wm * 64 + i * 16 + (l >> 2);
            int cn = n0 + wn * 32 + j * 8 + (l & 3) * 2;
            float2* p0 = (float2*)(C + (size_t)rm * N + cn);
            float2* p1 = (float2*)(C + (size_t)(rm + 8) * N + cn);
            float v0, v1, v2, v3;
            if (ACC){
                float2 o0 = *p0, o1 = *p1;
                v0 = acc[i][j][0] + o0.x; v1 = acc[i][j][1] + o0.y;
                v2 = acc[i][j][2] + o1.x; v3 = acc[i][j][3] + o1.y;
            } else {
                float b0 = bias[cn], b1 = bias[cn + 1];
                v0 = acc[i][j][0] + b0; v1 = acc[i][j][1] + b1;
                v2 = acc[i][j][2] + b0; v3 = acc[i][j][3] + b1;
                if (SIG){ v0 = sigf(v0); v1 = sigf(v1); v2 = sigf(v2); v3 = sigf(v3); }
            }
            *p0 = make_float2(v0, v1);
            *p1 = make_float2(v2, v3);
        }
    }
}

// ---------------- persistent LSTM recurrence ----------------
// 148 CTAs (1/SM), 224 threads = 7 warps. Warp w owns 2 h-elements -> 8 W_hh
// rows. K in [0,1024) of each row lives in REGISTERS (128 half2 per lane,
// loaded once); K in [1024,2048) streams from SMEM each step. Halves the
// per-step SMEM crossbar traffic. HFMA2 accumulate, fp32 flush every 4 j.
__global__ __launch_bounds__(RTHREADS, 1)
void lstm_rec_kernel(const float* __restrict__ Whh, const float* __restrict__ gx,
                     __half* __restrict__ hs, float* __restrict__ hbuf,
                     unsigned* __restrict__ bar){
    extern __shared__ uint2 smW2[];                   // [56][512] uint2 = 2048 fp16/row
    unsigned* smw32 = (unsigned*)smW2;
    const int tid = threadIdx.x;
    const int w = tid >> 5, l = tid & 31;
    const int cta = blockIdx.x;

    // load + convert this CTA's W_hh rows to fp16 in SMEM (row sr = local_e*4+gate)
    for (int idx = tid; idx < NROWS * 1024; idx += RTHREADS){
        int sr = idx >> 10, wc = idx & 1023;
        int e = cta * HPC + (sr >> 2);
        int gate = sr & 3;
        unsigned val = 0u;
        if (e < HID){
            const float2 f2 = *(const float2*)(Whh + (size_t)(gate * HID + e) * HID + 2 * wc);
            unsigned lo = (unsigned)__half_as_ushort(__float2half_rn(f2.x));
            unsigned hi = (unsigned)__half_as_ushort(__float2half_rn(f2.y));
            val = (hi << 16) | lo;
        }
        smw32[sr * 1024 + wc] = val;
    }
    // zero all replicas of h buffer 0
    if (tid < HPC){
        int e = cta * HPC + tid;
        if (e < HID){
            #pragma unroll
            for (int k = 0; k < NCOPY; ++k) hbuf[k * HID + e] = 0.0f;
        }
    }
    __syncthreads();

    const int rowbase = w * 8;                        // rows rowbase..rowbase+7
    // pull K-half-0 of this warp's 8 rows into registers (loop-invariant)
    __half2 wreg[8][16];
    #pragma unroll
    for (int r = 0; r < 8; ++r){
        #pragma unroll
        for (int j = 0; j < 8; ++j){
            uint2 wv = smW2[(rowbase + r) * 512 + l + 32 * j];
            wreg[r][2 * j]     = u2h2(wv.x);
            wreg[r][2 * j + 1] = u2h2(wv.y);
        }
    }

    if (tid == 0){
        red_release_add(bar);
        while (ld_acquire(bar) < (unsigned)NCTA) { }
    }
    __syncthreads();

    const int e0 = cta * HPC + 2 * w;
    const int e1 = e0 + 1;
    const bool a0 = (e0 < HID);
    const bool a1 = (e1 < HID);
    const int mycopy = (cta + w) & (NCOPY - 1);
    float c0 = 0.0f, c1 = 0.0f;

    #pragma unroll 1
    for (int t = 0; t < TT; ++t){
        const float4* hr4 = (const float4*)(hbuf + ((size_t)(t & 1) * NCOPY + mycopy) * HID);
        float* hwb = hbuf + (size_t)((t + 1) & 1) * NCOPY * HID;

        // gate input projections (uniform per-warp loads, independent of barrier timing)
        float gxe[8];
        #pragma unroll
        for (int g = 0; g < 4; ++g){
            gxe[g]     = a0 ? __ldcg(gx + (size_t)t * G4 + g * HID + e0) : 0.f;
            gxe[4 + g] = a1 ? __ldcg(gx + (size_t)t * G4 + g * HID + e1) : 0.f;
        }

        // coalesced h load + convert to half2 (two batches to cap register peak)
        __half2 hh[32];
        {
            float4 hv8[8];
            #pragma unroll
            for (int j = 0; j < 8; ++j) hv8[j] = __ldcg(hr4 + l + 32 * j);
            #pragma unroll
            for (int j = 0; j < 8; ++j){
                hh[2 * j]     = __floats2half2_rn(hv8[j].x, hv8[j].y);
                hh[2 * j + 1] = __floats2half2_rn(hv8[j].z, hv8[j].w);
            }
            #pragma unroll
            for (int j = 0; j < 8; ++j) hv8[j] = __ldcg(hr4 + l + 32 * (j + 8));
            #pragma unroll
            for (int j = 0; j < 8; ++j){
                hh[16 + 2 * j] = __floats2half2_rn(hv8[j].x, hv8[j].y);
                hh[17 + 2 * j] = __floats2half2_rn(hv8[j].z, hv8[j].w);
            }
        }

        float acc[8] = {0.f,0.f,0.f,0.f,0.f,0.f,0.f,0.f};
        #pragma unroll
        for (int ch = 0; ch < 4; ++ch){
            __half2 ha[8];
            #pragma unroll
            for (int r = 0; r < 8; ++r) ha[r] = __halves2half2(__ushort_as_half(0), __ushort_as_half(0));
            #pragma unroll
            for (int jj = 0; jj < 4; ++jj){
                const int j = ch * 4 + jj;
                const __half2 h01 = hh[2 * j], h23 = hh[2 * j + 1];
                if (j < 8){
                    #pragma unroll
                    for (int r = 0; r < 8; ++r){
                        ha[r] = __hfma2(wreg[r][2 * j], h01, ha[r]);
                        ha[r] = __hfma2(wreg[r][2 * j + 1], h23, ha[r]);
                    }
                } else {
                    #pragma unroll
                    for (int r = 0; r < 8; ++r){
                        uint2 wv = smW2[(rowbase + r) * 512 + l + 32 * j];
                        ha[r] = __hfma2(u2h2(wv.x), h01, ha[r]);
                        ha[r] = __hfma2(u2h2(wv.y), h23, ha[r]);
                    }
                }
            }
            #pragma unroll
            for (int r = 0; r < 8; ++r){
                float2 f2 = __half22float2(ha[r]);
                acc[r] += f2.x + f2.y;
            }
        }
        #pragma unroll
        for (int off = 16; off; off >>= 1){
            #pragma unroll
            for (int r = 0; r < 8; ++r)
                acc[r] += __shfl_xor_sync(0xffffffffu, acc[r], off);
        }

        // gate math for both elements (all lanes redundantly; uniform values)
        float ig0 = sigf(acc[0] + gxe[0]);
        float fg0 = sigf(acc[1] + gxe[1]);
        float gt0 = tanh_fast(acc[2] + gxe[2]);
        float og0 = sigf(acc[3] + gxe[3]);
        c0 = fg0 * c0 + ig0 * gt0;
        float hn0 = og0 * tanh_fast(c0);

        float ig1 = sigf(acc[4] + gxe[4]);
        float fg1 = sigf(acc[5] + gxe[5]);
        float gt1 = tanh_fast(acc[6] + gxe[6]);
        float og1 = sigf(acc[7] + gxe[7]);
        c1 = fg1 * c1 + ig1 * gt1;
        float hn1 = og1 * tanh_fast(c1);

        if (a0 && l < NCOPY)                 __stcg(&hwb[l * HID + e0], hn0);
        if (a1 && l >= NCOPY && l < 2*NCOPY) __stcg(&hwb[(l - NCOPY) * HID + e1], hn1);
        if (a0 && l == 0) __stcg(&hs[(size_t)t * HID + e0], __float2half(hn0));
        if (a1 && l == 1) __stcg(&hs[(size_t)t * HID + e1], __float2half(hn1));

        // grid barrier: release-arrive, every tid0 polls the counter directly
        __syncthreads();
        if (tid == 0){
            red_release_add(bar);
            const unsigned target = (unsigned)(t + 2) * (unsigned)NCTA;
            while (ld_acquire(bar) < target) { }
        }
        __syncthreads();
    }
}

// ---------------- launch ----------------
extern "C" void kernel_launch(void* const* d_in, const int* in_sizes, int n_in,
                              void* d_out, int out_size){
    const float* x    = (const float*)d_in[0];
    const float* W_ih = (const float*)d_in[1];
    const float* W_hh = (const float*)d_in[2];
    const float* b_ih = (const float*)d_in[3];
    const float* b_hh = (const float*)d_in[4];
    const float* Wo   = (const float*)d_in[5];
    const float* bo   = (const float*)d_in[6];
    float* out = (float*)d_out;

    unsigned char* base = nullptr;
    cudaGetSymbolAddress((void**)&base, g_scratch);
    float*    gx   = (float*)(base + OFF_GX);
    __half*   xh   = (__half*)(base + OFF_XH);
    __half*   xl   = (__half*)(base + OFF_XL);
    __half*   wih  = (__half*)(base + OFF_WIH);
    __half*   wil  = (__half*)(base + OFF_WIL);
    __half*   wo   = (__half*)(base + OFF_WO);
    __half*   hsb  = (__half*)(base + OFF_HS);
    float*    bias = (float*)(base + OFF_BIAS);
    float*    hbuf = (float*)(base + OFF_HBUF);
    unsigned* bar  = (unsigned*)(base + OFF_BAR);

    cudaFuncSetAttribute(lstm_rec_kernel,
                         cudaFuncAttributeMaxDynamicSharedMemorySize, REC_SMEM);

    setup_kernel<<<G4 / 256, 256>>>(b_ih, b_hh, bias, bar);
    f2h_split_kernel<<<1024, 256>>>(x,    xh,  xl,  TT * INW);
    f2h_split_kernel<<<1024, 256>>>(W_ih, wih, wil, G4 * INW);
    // Wo: lo residual not needed; dump into gx region, which GEMM #1 below
    // fully overwrites afterwards (same stream => ordered).
    f2h_split_kernel<<<1024, 256>>>(Wo, wo, (__half*)gx, INW * HID);

    dim3 g1(G4 / 128, TT / 128);
    gemm_nt_kernel<0, 0><<<g1, 256>>>(xh, wih, bias, gx, TT, G4, INW);
    gemm_nt_kernel<0, 1><<<g1, 256>>>(xl, wih, bias, gx, TT, G4, INW);
    gemm_nt_kernel<0, 1><<<g1, 256>>>(xh, wil, bias, gx, TT, G4, INW);

    lstm_rec_kernel<<<NCTA, RTHREADS, REC_SMEM>>>(W_hh, gx, hsb, hbuf, bar);

    dim3 g2(INW / 128, TT / 128);
    gemm_nt_kernel<1, 0><<<g2, 256>>>(hsb, wo, bo, out, TT, INW, HID);
}